// round 9
// baseline (speedup 1.0000x reference)
#include <cuda_runtime.h>
#include <cuda_bf16.h>
#include <cstdint>

// Problem constants
#define NUM_QT   65
#define NUM_OT   151
#define PAIR_NUM 90
#define BATCH    8192
#define BOX      10
#define TOTAL_ELEMS (NUM_QT * PAIR_NUM * NUM_OT * NUM_OT)  // 133,385,850
#define N4_TOTAL (TOTAL_ELEMS / 4)                         // 33,346,462 (tail = 2)

// ---------------------------------------------------------------------------
// Copy a float4 range [c4_lo, c4_hi) of score_matrix -> out.
// Simple grid-stride (R1 formulation — best measured bandwidth).
// Last chunk also copies the scalar tail (TOTAL_ELEMS - 4*N4_TOTAL = 2 elems).
// ---------------------------------------------------------------------------
__global__ void __launch_bounds__(256) copy_chunk_kernel(
    const float4* __restrict__ src4,
    float4* __restrict__ dst4,
    const float* __restrict__ src,
    float* __restrict__ dst,
    int c4_lo, int c4_hi, int do_tail)
{
    const int stride = gridDim.x * blockDim.x;
    for (int i = c4_lo + blockIdx.x * blockDim.x + threadIdx.x; i < c4_hi; i += stride) {
        dst4[i] = src4[i];
    }
    if (do_tail && blockIdx.x == 0 && threadIdx.x < (TOTAL_ELEMS - 4 * N4_TOTAL)) {
        int e = 4 * N4_TOTAL + threadIdx.x;
        dst[e] = src[e];
    }
}

// ---------------------------------------------------------------------------
// Scatter-add attention products restricted to output offsets in [lo, hi).
// One thread per (batch, pair). pair p -> i = p/9, j' = p%9, j = j' + (j' >= i).
// out[qt[b]][p][label[b,j]][label[b,i]] += att[b,i]*att[b,j]
// atomicAdd result unused -> REDG (fire-and-forget).
// ---------------------------------------------------------------------------
__global__ void __launch_bounds__(256) scatter_chunk_kernel(
    const int* __restrict__ obj_label,
    const int* __restrict__ qus_type,
    const float* __restrict__ attention,
    float* __restrict__ out,
    long long lo, long long hi)
{
    int idx = blockIdx.x * blockDim.x + threadIdx.x;
    if (idx >= BATCH * PAIR_NUM) return;

    int b = idx / PAIR_NUM;
    int p = idx - b * PAIR_NUM;
    int i = p / (BOX - 1);
    int jr = p - i * (BOX - 1);
    int j = jr + (jr >= i ? 1 : 0);

    int qt  = __ldg(&qus_type[b]);
    int oli = __ldg(&obj_label[b * BOX + i]);
    int olj = __ldg(&obj_label[b * BOX + j]);

    long long off = ((long long)(qt * PAIR_NUM + p) * NUM_OT + olj) * NUM_OT + oli;
    if (off < lo || off >= hi) return;

    float ai = __ldg(&attention[b * BOX + i]);
    float aj = __ldg(&attention[b * BOX + j]);
    atomicAdd(out + off, ai * aj);
}

// ---------------------------------------------------------------------------
// Launch: asymmetric 2-chunk pipeline (7/8 + 1/8).
//   stream 0: copy chunk0 (7/8), copy chunk1 (1/8)
//   side:     scatter chunk0 after copy0 (overlaps copy1), scatter chunk1 after copy1
// Exposed post-copy work = scatter chunk1 (~1/8 of updates, ~2-3us).
//
// Inputs (metadata order):
//   d_in[0] = obj_label    int32   [8192,10]
//   d_in[1] = qus_type     int32   [8192]
//   d_in[2] = attention    float32 [8192,10]
//   d_in[3] = score_matrix float32 [65,90,151,151]
// ---------------------------------------------------------------------------
extern "C" void kernel_launch(void* const* d_in, const int* in_sizes, int n_in,
                              void* d_out, int out_size)
{
    const int*   obj_label = (const int*)d_in[0];
    const int*   qus_type  = (const int*)d_in[1];
    const float* attention = (const float*)d_in[2];
    const float* score     = (const float*)d_in[3];
    float*       out       = (float*)d_out;

    // Lazy one-time resource setup (first call = uncaptured correctness run).
    static cudaStream_t s_side = nullptr;
    static cudaEvent_t  ev0 = nullptr, ev1 = nullptr, ev_join = nullptr;
    if (s_side == nullptr) {
        cudaStreamCreateWithFlags(&s_side, cudaStreamNonBlocking);
        cudaEventCreateWithFlags(&ev0, cudaEventDisableTiming);
        cudaEventCreateWithFlags(&ev1, cudaEventDisableTiming);
        cudaEventCreateWithFlags(&ev_join, cudaEventDisableTiming);
    }

    const int copy_blocks = 148 * 16;
    const int scat_total  = BATCH * PAIR_NUM;          // 737,280
    const int scat_blocks = (scat_total + 255) / 256;

    // Split at 7/8 of the float4 range.
    const int c4_split = (int)(((long long)N4_TOTAL * 7) / 8);
    const long long e_split = (long long)c4_split * 4;

    // Copy chunk0 (7/8)
    copy_chunk_kernel<<<copy_blocks, 256, 0, 0>>>(
        (const float4*)score, (float4*)out, score, out, 0, c4_split, 0);
    cudaEventRecord(ev0, 0);

    // Copy chunk1 (1/8 + tail) — runs while scatter chunk0 executes on side stream.
    copy_chunk_kernel<<<copy_blocks, 256, 0, 0>>>(
        (const float4*)score, (float4*)out, score, out, c4_split, N4_TOTAL, 1);
    cudaEventRecord(ev1, 0);

    // Scatter chunk0: offsets [0, e_split), after copy chunk0.
    cudaStreamWaitEvent(s_side, ev0, 0);
    scatter_chunk_kernel<<<scat_blocks, 256, 0, s_side>>>(
        obj_label, qus_type, attention, out, 0, e_split);

    // Scatter chunk1: offsets [e_split, TOTAL), after copy chunk1.
    cudaStreamWaitEvent(s_side, ev1, 0);
    scatter_chunk_kernel<<<scat_blocks, 256, 0, s_side>>>(
        obj_label, qus_type, attention, out, e_split, (long long)TOTAL_ELEMS);

    // Join side stream back into the capture origin stream.
    cudaEventRecord(ev_join, s_side);
    cudaStreamWaitEvent(0, ev_join, 0);
}